// round 3
// baseline (speedup 1.0000x reference)
#include <cuda_runtime.h>
#include <math.h>

#define NN   20000
#define NE   320000
#define FIN  6
#define HID  128
#define NCLS 21
#define NL   4
#define NG   16
#define EPSV 1e-5f

// ---------------- scratch (device globals; no runtime allocation) ----------
__device__ float g_e[NE * NG];        // RBF expansion        [E,16]
__device__ float g_h[NN * HID];       // node features        [N,128]
__device__ float g_pfi[NN * HID];     // h @ Wf[0:128]   (dst/x_i path, f)
__device__ float g_pfj[NN * HID];     // h @ Wf[128:256] (src/x_j path, f)
__device__ float g_psi[NN * HID];     // h @ Ws[0:128]
__device__ float g_psj[NN * HID];     // h @ Ws[128:256]
__device__ float g_agg[NN * HID];     // message aggregation
__device__ float g_cstat[2 * HID];    // column sum / sumsq for BN
__device__ float g_bnsc[HID];         // BN scale
__device__ float g_bnsh[HID];         // BN shift

// ---------------- RBF expansion: e[k] = exp(coeff*(d - 8k/15)^2) -----------
__global__ void k_rbf(const float* __restrict__ dist) {
    int e = blockIdx.x * blockDim.x + threadIdx.x;
    if (e >= NE) return;
    float d = dist[e];
    const float coeff = -1.7578125f;           // -0.5 / (8/15)^2
    const float step  = 8.0f / 15.0f;
    float4* p = reinterpret_cast<float4*>(g_e + (size_t)e * NG);
#pragma unroll
    for (int j = 0; j < 4; j++) {
        float4 v;
        float dd;
        dd = d - (4 * j + 0) * step; v.x = __expf(coeff * dd * dd);
        dd = d - (4 * j + 1) * step; v.y = __expf(coeff * dd * dd);
        dd = d - (4 * j + 2) * step; v.z = __expf(coeff * dd * dd);
        dd = d - (4 * j + 3) * step; v.w = __expf(coeff * dd * dd);
        p[j] = v;
    }
}

// ---------------- node embedding: h = x @ W_node + b_node ------------------
__global__ __launch_bounds__(HID) void k_embed(const float* __restrict__ x,
                                               const float* __restrict__ Wn,
                                               const float* __restrict__ bn) {
    int n = blockIdx.x, c = threadIdx.x;
    const float* xr = x + (size_t)n * FIN;
    float a = bn[c];
#pragma unroll
    for (int k = 0; k < FIN; k++) a = fmaf(__ldg(&xr[k]), Wn[k * HID + c], a);
    g_h[(size_t)n * HID + c] = a;
}

// ---------------- per-node projections (warp per node, float4 cols) --------
__global__ __launch_bounds__(256) void k_proj(const float* __restrict__ Wf,
                                              const float* __restrict__ Ws,
                                              int l) {
    int gw = (blockIdx.x * blockDim.x + threadIdx.x) >> 5;   // node
    int lane = threadIdx.x & 31;
    if (gw >= NN) return;
    const float* bfp = Wf + (size_t)l * 272 * HID;
    const float* bsp = Ws + (size_t)l * 272 * HID;
    const float4* Wfi = reinterpret_cast<const float4*>(bfp);
    const float4* Wfj = reinterpret_cast<const float4*>(bfp + HID * HID);
    const float4* Wsi = reinterpret_cast<const float4*>(bsp);
    const float4* Wsj = reinterpret_cast<const float4*>(bsp + HID * HID);
    const float* hrow = g_h + (size_t)gw * HID;
    float h0 = hrow[lane], h1 = hrow[lane + 32], h2 = hrow[lane + 64], h3 = hrow[lane + 96];
    float hregs[4] = {h0, h1, h2, h3};
    float4 afi = make_float4(0.f, 0.f, 0.f, 0.f);
    float4 afj = afi, asi = afi, asj = afi;
#pragma unroll
    for (int ch = 0; ch < 4; ch++) {
        float hs = hregs[ch];
#pragma unroll
        for (int kk = 0; kk < 32; kk++) {
            float hk = __shfl_sync(0xffffffffu, hs, kk);
            int k = ch * 32 + kk;
            float4 w;
            w = Wfi[k * 32 + lane];
            afi.x = fmaf(hk, w.x, afi.x); afi.y = fmaf(hk, w.y, afi.y);
            afi.z = fmaf(hk, w.z, afi.z); afi.w = fmaf(hk, w.w, afi.w);
            w = Wfj[k * 32 + lane];
            afj.x = fmaf(hk, w.x, afj.x); afj.y = fmaf(hk, w.y, afj.y);
            afj.z = fmaf(hk, w.z, afj.z); afj.w = fmaf(hk, w.w, afj.w);
            w = Wsi[k * 32 + lane];
            asi.x = fmaf(hk, w.x, asi.x); asi.y = fmaf(hk, w.y, asi.y);
            asi.z = fmaf(hk, w.z, asi.z); asi.w = fmaf(hk, w.w, asi.w);
            w = Wsj[k * 32 + lane];
            asj.x = fmaf(hk, w.x, asj.x); asj.y = fmaf(hk, w.y, asj.y);
            asj.z = fmaf(hk, w.z, asj.z); asj.w = fmaf(hk, w.w, asj.w);
        }
    }
    reinterpret_cast<float4*>(g_pfi + (size_t)gw * HID)[lane] = afi;
    reinterpret_cast<float4*>(g_pfj + (size_t)gw * HID)[lane] = afj;
    reinterpret_cast<float4*>(g_psi + (size_t)gw * HID)[lane] = asi;
    reinterpret_cast<float4*>(g_psj + (size_t)gw * HID)[lane] = asj;
}

// ---------------- edge message + scatter-add -------------------------------
#define EPB 128
__global__ __launch_bounds__(HID) void k_edge(const int* __restrict__ eidx,
                                              const float* __restrict__ Wf,
                                              const float* __restrict__ bf,
                                              const float* __restrict__ Ws,
                                              const float* __restrict__ bs,
                                              int l) {
    int c = threadIdx.x;
    const float* Wfe = Wf + (size_t)l * 272 * HID + 256 * HID;
    const float* Wse = Ws + (size_t)l * 272 * HID + 256 * HID;
    float wfe[NG], wse[NG];
#pragma unroll
    for (int k = 0; k < NG; k++) {
        wfe[k] = __ldg(&Wfe[k * HID + c]);
        wse[k] = __ldg(&Wse[k * HID + c]);
    }
    float bfc = __ldg(&bf[l * HID + c]);
    float bsc = __ldg(&bs[l * HID + c]);
    int e0 = blockIdx.x * EPB;
    for (int i = 0; i < EPB; i++) {
        int e = e0 + i;
        int src = __ldg(&eidx[e]);        // edge_index[0] = x_j
        int dst = __ldg(&eidx[NE + e]);   // edge_index[1] = x_i, agg target
        const float4* ep = reinterpret_cast<const float4*>(g_e + (size_t)e * NG);
        float4 ea = ep[0], eb = ep[1], ec = ep[2], ed = ep[3];
        float zf = g_pfi[(size_t)dst * HID + c] + g_pfj[(size_t)src * HID + c] + bfc;
        float zs = g_psi[(size_t)dst * HID + c] + g_psj[(size_t)src * HID + c] + bsc;
        zf = fmaf(ea.x, wfe[0], zf);  zf = fmaf(ea.y, wfe[1], zf);
        zf = fmaf(ea.z, wfe[2], zf);  zf = fmaf(ea.w, wfe[3], zf);
        zf = fmaf(eb.x, wfe[4], zf);  zf = fmaf(eb.y, wfe[5], zf);
        zf = fmaf(eb.z, wfe[6], zf);  zf = fmaf(eb.w, wfe[7], zf);
        zf = fmaf(ec.x, wfe[8], zf);  zf = fmaf(ec.y, wfe[9], zf);
        zf = fmaf(ec.z, wfe[10], zf); zf = fmaf(ec.w, wfe[11], zf);
        zf = fmaf(ed.x, wfe[12], zf); zf = fmaf(ed.y, wfe[13], zf);
        zf = fmaf(ed.z, wfe[14], zf); zf = fmaf(ed.w, wfe[15], zf);
        zs = fmaf(ea.x, wse[0], zs);  zs = fmaf(ea.y, wse[1], zs);
        zs = fmaf(ea.z, wse[2], zs);  zs = fmaf(ea.w, wse[3], zs);
        zs = fmaf(eb.x, wse[4], zs);  zs = fmaf(eb.y, wse[5], zs);
        zs = fmaf(eb.z, wse[6], zs);  zs = fmaf(eb.w, wse[7], zs);
        zs = fmaf(ec.x, wse[8], zs);  zs = fmaf(ec.y, wse[9], zs);
        zs = fmaf(ec.z, wse[10], zs); zs = fmaf(ec.w, wse[11], zs);
        zs = fmaf(ed.x, wse[12], zs); zs = fmaf(ed.y, wse[13], zs);
        zs = fmaf(ed.z, wse[14], zs); zs = fmaf(ed.w, wse[15], zs);
        float fgate = __fdividef(1.0f, 1.0f + __expf(-zf));
        float sp = fmaxf(zs, 0.0f) + __logf(1.0f + __expf(-fabsf(zs)));
        atomicAdd(&g_agg[(size_t)dst * HID + c], fgate * sp);
    }
}

// ---------------- BN column stats ------------------------------------------
__global__ __launch_bounds__(HID) void k_bnred() {
    int c = threadIdx.x;
    float s = 0.f, q = 0.f;
    for (int n = blockIdx.x; n < NN; n += gridDim.x) {
        float v = g_agg[(size_t)n * HID + c];
        s += v; q = fmaf(v, v, q);
    }
    atomicAdd(&g_cstat[c], s);
    atomicAdd(&g_cstat[HID + c], q);
}

__global__ void k_bnfin(const float* __restrict__ bn_g,
                        const float* __restrict__ bn_b, int l) {
    int c = threadIdx.x;
    float mu = g_cstat[c] * (1.0f / NN);
    float var = g_cstat[HID + c] * (1.0f / NN) - mu * mu;
    float sc = bn_g[l * HID + c] * rsqrtf(var + EPSV);
    g_bnsc[c] = sc;
    g_bnsh[c] = fmaf(-mu, sc, bn_b[l * HID + c]);
}

// ---------------- fused BN-apply + residual + LayerNorm + ReLU + residual --
__global__ __launch_bounds__(HID) void k_update(const float* __restrict__ ln_g,
                                                const float* __restrict__ ln_b,
                                                int l) {
    int n = blockIdx.x, c = threadIdx.x;
    float h = g_h[(size_t)n * HID + c];
    float v = fmaf(g_agg[(size_t)n * HID + c], g_bnsc[c], g_bnsh[c]) + h;
    float s = v, q = v * v;
#pragma unroll
    for (int o = 16; o > 0; o >>= 1) {
        s += __shfl_xor_sync(0xffffffffu, s, o);
        q += __shfl_xor_sync(0xffffffffu, q, o);
    }
    __shared__ float ss[4], sq[4], smv[2];
    int w = c >> 5;
    if ((c & 31) == 0) { ss[w] = s; sq[w] = q; }
    __syncthreads();
    if (c == 0) {
        float ts = ss[0] + ss[1] + ss[2] + ss[3];
        float tq = sq[0] + sq[1] + sq[2] + sq[3];
        float m = ts * (1.0f / HID);
        float var = tq * (1.0f / HID) - m * m;
        smv[0] = m; smv[1] = rsqrtf(var + EPSV);
    }
    __syncthreads();
    float hn = fmaf((v - smv[0]) * smv[1], ln_g[l * HID + c], ln_b[l * HID + c]);
    g_h[(size_t)n * HID + c] = fmaxf(hn, 0.0f) + h;
}

// ---------------- final LayerNorm + FC -------------------------------------
__global__ __launch_bounds__(HID) void k_out(const float* __restrict__ lng,
                                             const float* __restrict__ lnb,
                                             const float* __restrict__ Wfc,
                                             const float* __restrict__ bfc,
                                             float* __restrict__ out) {
    int n = blockIdx.x, c = threadIdx.x;
    float h = g_h[(size_t)n * HID + c];
    float s = h, q = h * h;
#pragma unroll
    for (int o = 16; o > 0; o >>= 1) {
        s += __shfl_xor_sync(0xffffffffu, s, o);
        q += __shfl_xor_sync(0xffffffffu, q, o);
    }
    __shared__ float ss[4], sq[4], smv[2];
    __shared__ float sh[HID];
    int w = c >> 5;
    if ((c & 31) == 0) { ss[w] = s; sq[w] = q; }
    __syncthreads();
    if (c == 0) {
        float ts = ss[0] + ss[1] + ss[2] + ss[3];
        float tq = sq[0] + sq[1] + sq[2] + sq[3];
        float m = ts * (1.0f / HID);
        float var = tq * (1.0f / HID) - m * m;
        smv[0] = m; smv[1] = rsqrtf(var + EPSV);
    }
    __syncthreads();
    sh[c] = fmaf((h - smv[0]) * smv[1], lng[c], lnb[c]);
    __syncthreads();
    if (c < NCLS) {
        float a = bfc[c];
#pragma unroll 16
        for (int k = 0; k < HID; k++) a = fmaf(sh[k], Wfc[k * NCLS + c], a);
        out[(size_t)n * NCLS + c] = a;
    }
}

// ---------------- launch ----------------------------------------------------
extern "C" void kernel_launch(void* const* d_in, const int* in_sizes, int n_in,
                              void* d_out, int out_size) {
    const float* x    = (const float*)d_in[0];
    const int*   eidx = (const int*)  d_in[1];
    const float* dist = (const float*)d_in[2];
    const float* Wn   = (const float*)d_in[3];
    const float* bn   = (const float*)d_in[4];
    const float* Wf   = (const float*)d_in[5];
    const float* bf   = (const float*)d_in[6];
    const float* Ws   = (const float*)d_in[7];
    const float* bs   = (const float*)d_in[8];
    const float* bng  = (const float*)d_in[9];
    const float* bnb  = (const float*)d_in[10];
    const float* lng  = (const float*)d_in[11];
    const float* lnb  = (const float*)d_in[12];
    const float* log_ = (const float*)d_in[13];
    const float* lob  = (const float*)d_in[14];
    const float* Wfc  = (const float*)d_in[15];
    const float* bfc  = (const float*)d_in[16];
    float* out = (float*)d_out;

    void *aggp, *cstatp;
    cudaGetSymbolAddress(&aggp, g_agg);
    cudaGetSymbolAddress(&cstatp, g_cstat);

    k_rbf<<<(NE + 255) / 256, 256>>>(dist);
    k_embed<<<NN, HID>>>(x, Wn, bn);
    for (int l = 0; l < NL; l++) {
        k_proj<<<(NN * 32) / 256, 256>>>(Wf, Ws, l);
        cudaMemsetAsync(aggp, 0, (size_t)NN * HID * sizeof(float));
        cudaMemsetAsync(cstatp, 0, 2 * HID * sizeof(float));
        k_edge<<<NE / EPB, HID>>>(eidx, Wf, bf, Ws, bs, l);
        k_bnred<<<256, HID>>>();
        k_bnfin<<<1, HID>>>(bng, bnb, l);
        k_update<<<NN, HID>>>(lng, lnb, l);
    }
    k_out<<<NN, HID>>>(log_, lob, Wfc, bfc, out);
}

// round 4
// speedup vs baseline: 1.0202x; 1.0202x over previous
#include <cuda_runtime.h>
#include <math.h>

#define NN   20000
#define NE   320000
#define FIN  6
#define HID  128
#define NCLS 21
#define NL   4
#define NG   16
#define EPSV 1e-5f
#define NPB  4          // nodes per block in edge kernel

// ---------------- scratch (device globals; no runtime allocation) ----------
__device__ float g_e[NE * NG];         // RBF expansion, CSR edge order [E,16]
__device__ float g_h[NN * HID];        // node features
__device__ float g_pi[NN * HID * 2];   // interleaved (f,s) dst-path projection
__device__ float g_pj[NN * HID * 2];   // interleaved (f,s) src-path projection
__device__ float g_agg[NN * HID];      // aggregated messages
__device__ float g_cstat[2 * HID];     // BN column sum / sumsq
__device__ float g_bnsc[HID];
__device__ float g_bnsh[HID];
__device__ int   g_rowptr[NN + 1];     // CSR row pointers (by dst)
__device__ int   g_cursor[NN];         // degree counter / scatter cursor
__device__ int   g_csrc[NE];           // src node per CSR slot
__device__ int   g_ceid[NE];           // original edge id per CSR slot

// ---------------- CSR build ------------------------------------------------
__global__ void k_hist(const int* __restrict__ eidx) {
    int e = blockIdx.x * blockDim.x + threadIdx.x;
    if (e < NE) atomicAdd(&g_cursor[eidx[NE + e]], 1);
}

__global__ void k_scan() {   // single block, 1024 threads, NN=20000 -> 20/thread
    __shared__ int sp_[1024];
    int t = threadIdx.x;
    const int CH = 20;
    int base = t * CH;
    int lim = min(base + CH, NN);
    int sum = 0;
    for (int i = base; i < lim; i++) sum += g_cursor[i];
    sp_[t] = sum;
    __syncthreads();
    for (int off = 1; off < 1024; off <<= 1) {
        int v = (t >= off) ? sp_[t - off] : 0;
        __syncthreads();
        sp_[t] += v;
        __syncthreads();
    }
    int run = (t > 0) ? sp_[t - 1] : 0;
    for (int i = base; i < lim; i++) {
        int d = g_cursor[i];
        g_rowptr[i] = run;
        g_cursor[i] = run;   // reset cursor to row start for scatter
        run += d;
    }
    if (t == 0) g_rowptr[NN] = NE;
}

__global__ void k_scatter(const int* __restrict__ eidx) {
    int e = blockIdx.x * blockDim.x + threadIdx.x;
    if (e >= NE) return;
    int src = eidx[e];
    int dst = eidx[NE + e];
    int pos = atomicAdd(&g_cursor[dst], 1);
    g_csrc[pos] = src;
    g_ceid[pos] = e;
}

// ---------------- RBF expansion in CSR order -------------------------------
__global__ void k_rbf(const float* __restrict__ dist) {
    int i = blockIdx.x * blockDim.x + threadIdx.x;
    if (i >= NE) return;
    float d = dist[g_ceid[i]];
    const float coeff = -1.7578125f;            // -0.5 / (8/15)^2
    const float step  = 8.0f / 15.0f;
    float4* p = reinterpret_cast<float4*>(g_e + (size_t)i * NG);
#pragma unroll
    for (int j = 0; j < 4; j++) {
        float4 v;
        float dd;
        dd = d - (4 * j + 0) * step; v.x = __expf(coeff * dd * dd);
        dd = d - (4 * j + 1) * step; v.y = __expf(coeff * dd * dd);
        dd = d - (4 * j + 2) * step; v.z = __expf(coeff * dd * dd);
        dd = d - (4 * j + 3) * step; v.w = __expf(coeff * dd * dd);
        p[j] = v;
    }
}

// ---------------- node embedding -------------------------------------------
__global__ __launch_bounds__(HID) void k_embed(const float* __restrict__ x,
                                               const float* __restrict__ Wn,
                                               const float* __restrict__ bn) {
    int n = blockIdx.x, c = threadIdx.x;
    const float* xr = x + (size_t)n * FIN;
    float a = bn[c];
#pragma unroll
    for (int k = 0; k < FIN; k++) a = fmaf(__ldg(&xr[k]), Wn[k * HID + c], a);
    g_h[(size_t)n * HID + c] = a;
}

// ---------------- per-node projections, interleaved (f,s) output -----------
__global__ __launch_bounds__(256) void k_proj(const float* __restrict__ Wf,
                                              const float* __restrict__ Ws,
                                              int l) {
    int gw = (blockIdx.x * blockDim.x + threadIdx.x) >> 5;   // node
    int lane = threadIdx.x & 31;
    if (gw >= NN) return;
    const float* bfp = Wf + (size_t)l * 272 * HID;
    const float* bsp = Ws + (size_t)l * 272 * HID;
    const float4* Wfi = reinterpret_cast<const float4*>(bfp);
    const float4* Wfj = reinterpret_cast<const float4*>(bfp + HID * HID);
    const float4* Wsi = reinterpret_cast<const float4*>(bsp);
    const float4* Wsj = reinterpret_cast<const float4*>(bsp + HID * HID);
    const float* hrow = g_h + (size_t)gw * HID;
    float hregs[4] = {hrow[lane], hrow[lane + 32], hrow[lane + 64], hrow[lane + 96]};
    float4 afi = make_float4(0.f, 0.f, 0.f, 0.f);
    float4 afj = afi, asi = afi, asj = afi;
#pragma unroll
    for (int ch = 0; ch < 4; ch++) {
        float hs = hregs[ch];
#pragma unroll
        for (int kk = 0; kk < 32; kk++) {
            float hk = __shfl_sync(0xffffffffu, hs, kk);
            int k = ch * 32 + kk;
            float4 w;
            w = Wfi[k * 32 + lane];
            afi.x = fmaf(hk, w.x, afi.x); afi.y = fmaf(hk, w.y, afi.y);
            afi.z = fmaf(hk, w.z, afi.z); afi.w = fmaf(hk, w.w, afi.w);
            w = Wfj[k * 32 + lane];
            afj.x = fmaf(hk, w.x, afj.x); afj.y = fmaf(hk, w.y, afj.y);
            afj.z = fmaf(hk, w.z, afj.z); afj.w = fmaf(hk, w.w, afj.w);
            w = Wsi[k * 32 + lane];
            asi.x = fmaf(hk, w.x, asi.x); asi.y = fmaf(hk, w.y, asi.y);
            asi.z = fmaf(hk, w.z, asi.z); asi.w = fmaf(hk, w.w, asi.w);
            w = Wsj[k * 32 + lane];
            asj.x = fmaf(hk, w.x, asj.x); asj.y = fmaf(hk, w.y, asj.y);
            asj.z = fmaf(hk, w.z, asj.z); asj.w = fmaf(hk, w.w, asj.w);
        }
    }
    // interleave: [node][col]{f,s}; thread owns cols 4*lane..4*lane+3
    float4* di = reinterpret_cast<float4*>(g_pi + (size_t)gw * (2 * HID) + 8 * lane);
    float4* dj = reinterpret_cast<float4*>(g_pj + (size_t)gw * (2 * HID) + 8 * lane);
    di[0] = make_float4(afi.x, asi.x, afi.y, asi.y);
    di[1] = make_float4(afi.z, asi.z, afi.w, asi.w);
    dj[0] = make_float4(afj.x, asj.x, afj.y, asj.y);
    dj[1] = make_float4(afj.z, asj.z, afj.w, asj.w);
}

// ---------------- CSR edge aggregation (no atomics) + fused BN stats -------
__global__ __launch_bounds__(HID) void k_edge(const float* __restrict__ Wf,
                                              const float* __restrict__ bf,
                                              const float* __restrict__ Ws,
                                              const float* __restrict__ bs,
                                              int l) {
    __shared__ float4 se[512];     // up to 128 edges * 16 floats of RBF
    __shared__ int ssrc[128];
    int c = threadIdx.x;
    const float* Wfe = Wf + (size_t)l * 272 * HID + 256 * HID;
    const float* Wse = Ws + (size_t)l * 272 * HID + 256 * HID;
    float wfe[NG], wse[NG];
#pragma unroll
    for (int k = 0; k < NG; k++) {
        wfe[k] = __ldg(&Wfe[k * HID + c]);
        wse[k] = __ldg(&Wse[k * HID + c]);
    }
    float bfc = __ldg(&bf[l * HID + c]);
    float bsc = __ldg(&bs[l * HID + c]);
    for (int nn = 0; nn < NPB; nn++) {
        int n = blockIdx.x * NPB + nn;
        float2 pi = *reinterpret_cast<const float2*>(g_pi + (size_t)n * (2 * HID) + 2 * c);
        float zfb = pi.x + bfc;
        float zsb = pi.y + bsc;
        int start = g_rowptr[n], end = g_rowptr[n + 1];
        float acc = 0.f;
        for (int j0 = start; j0 < end; j0 += 128) {
            int cnt = min(128, end - j0);
            if (c < cnt) ssrc[c] = g_csrc[j0 + c];
            const float4* ge4 = reinterpret_cast<const float4*>(g_e) + (size_t)j0 * 4;
            for (int t = c; t < cnt * 4; t += HID) se[t] = ge4[t];
            __syncthreads();
#pragma unroll 2
            for (int i = 0; i < cnt; i++) {
                int s = ssrc[i];
                float2 pj = *reinterpret_cast<const float2*>(g_pj + (size_t)s * (2 * HID) + 2 * c);
                float4 ea = se[i * 4 + 0], eb = se[i * 4 + 1];
                float4 ec = se[i * 4 + 2], ed = se[i * 4 + 3];
                float zf = zfb + pj.x;
                float zs = zsb + pj.y;
                float f0 = fmaf(ea.x, wfe[0],  fmaf(ea.y, wfe[1],  fmaf(ea.z, wfe[2],  ea.w * wfe[3])));
                float f1 = fmaf(eb.x, wfe[4],  fmaf(eb.y, wfe[5],  fmaf(eb.z, wfe[6],  eb.w * wfe[7])));
                float f2 = fmaf(ec.x, wfe[8],  fmaf(ec.y, wfe[9],  fmaf(ec.z, wfe[10], ec.w * wfe[11])));
                float f3 = fmaf(ed.x, wfe[12], fmaf(ed.y, wfe[13], fmaf(ed.z, wfe[14], ed.w * wfe[15])));
                float s0 = fmaf(ea.x, wse[0],  fmaf(ea.y, wse[1],  fmaf(ea.z, wse[2],  ea.w * wse[3])));
                float s1 = fmaf(eb.x, wse[4],  fmaf(eb.y, wse[5],  fmaf(eb.z, wse[6],  eb.w * wse[7])));
                float s2 = fmaf(ec.x, wse[8],  fmaf(ec.y, wse[9],  fmaf(ec.z, wse[10], ec.w * wse[11])));
                float s3 = fmaf(ed.x, wse[12], fmaf(ed.y, wse[13], fmaf(ed.z, wse[14], ed.w * wse[15])));
                zf += (f0 + f1) + (f2 + f3);
                zs += (s0 + s1) + (s2 + s3);
                float fg = __fdividef(1.0f, 1.0f + __expf(-zf));
                float sp = fmaxf(zs, 0.0f) + __logf(1.0f + __expf(-fabsf(zs)));
                acc = fmaf(fg, sp, acc);
            }
            __syncthreads();
        }
        g_agg[(size_t)n * HID + c] = acc;
        atomicAdd(&g_cstat[c], acc);              // REDG, fire-and-forget
        atomicAdd(&g_cstat[HID + c], acc * acc);
    }
}

// ---------------- BN finalize (also zeros cstat for next layer) ------------
__global__ void k_bnfin(const float* __restrict__ bn_g,
                        const float* __restrict__ bn_b, int l) {
    int c = threadIdx.x;
    float sum = g_cstat[c], sq = g_cstat[HID + c];
    g_cstat[c] = 0.f;
    g_cstat[HID + c] = 0.f;
    float mu = sum * (1.0f / NN);
    float var = sq * (1.0f / NN) - mu * mu;
    float sc = bn_g[l * HID + c] * rsqrtf(var + EPSV);
    g_bnsc[c] = sc;
    g_bnsh[c] = fmaf(-mu, sc, bn_b[l * HID + c]);
}

// ---------------- fused BN-apply + residual + LayerNorm + ReLU + residual --
__global__ __launch_bounds__(HID) void k_update(const float* __restrict__ ln_g,
                                                const float* __restrict__ ln_b,
                                                int l) {
    int n = blockIdx.x, c = threadIdx.x;
    float h = g_h[(size_t)n * HID + c];
    float v = fmaf(g_agg[(size_t)n * HID + c], g_bnsc[c], g_bnsh[c]) + h;
    float s = v, q = v * v;
#pragma unroll
    for (int o = 16; o > 0; o >>= 1) {
        s += __shfl_xor_sync(0xffffffffu, s, o);
        q += __shfl_xor_sync(0xffffffffu, q, o);
    }
    __shared__ float ss[4], sq[4], smv[2];
    int w = c >> 5;
    if ((c & 31) == 0) { ss[w] = s; sq[w] = q; }
    __syncthreads();
    if (c == 0) {
        float ts = ss[0] + ss[1] + ss[2] + ss[3];
        float tq = sq[0] + sq[1] + sq[2] + sq[3];
        float m = ts * (1.0f / HID);
        float var = tq * (1.0f / HID) - m * m;
        smv[0] = m; smv[1] = rsqrtf(var + EPSV);
    }
    __syncthreads();
    float hn = fmaf((v - smv[0]) * smv[1], ln_g[l * HID + c], ln_b[l * HID + c]);
    g_h[(size_t)n * HID + c] = fmaxf(hn, 0.0f) + h;
}

// ---------------- final LayerNorm + FC -------------------------------------
__global__ __launch_bounds__(HID) void k_out(const float* __restrict__ lng,
                                             const float* __restrict__ lnb,
                                             const float* __restrict__ Wfc,
                                             const float* __restrict__ bfc,
                                             float* __restrict__ out) {
    int n = blockIdx.x, c = threadIdx.x;
    float h = g_h[(size_t)n * HID + c];
    float s = h, q = h * h;
#pragma unroll
    for (int o = 16; o > 0; o >>= 1) {
        s += __shfl_xor_sync(0xffffffffu, s, o);
        q += __shfl_xor_sync(0xffffffffu, q, o);
    }
    __shared__ float ss[4], sq[4], smv[2];
    __shared__ float sh[HID];
    int w = c >> 5;
    if ((c & 31) == 0) { ss[w] = s; sq[w] = q; }
    __syncthreads();
    if (c == 0) {
        float ts = ss[0] + ss[1] + ss[2] + ss[3];
        float tq = sq[0] + sq[1] + sq[2] + sq[3];
        float m = ts * (1.0f / HID);
        float var = tq * (1.0f / HID) - m * m;
        smv[0] = m; smv[1] = rsqrtf(var + EPSV);
    }
    __syncthreads();
    sh[c] = fmaf((h - smv[0]) * smv[1], lng[c], lnb[c]);
    __syncthreads();
    if (c < NCLS) {
        float a = bfc[c];
#pragma unroll 16
        for (int k = 0; k < HID; k++) a = fmaf(sh[k], Wfc[k * NCLS + c], a);
        out[(size_t)n * NCLS + c] = a;
    }
}

// ---------------- launch ----------------------------------------------------
extern "C" void kernel_launch(void* const* d_in, const int* in_sizes, int n_in,
                              void* d_out, int out_size) {
    const float* x    = (const float*)d_in[0];
    const int*   eidx = (const int*)  d_in[1];
    const float* dist = (const float*)d_in[2];
    const float* Wn   = (const float*)d_in[3];
    const float* bn   = (const float*)d_in[4];
    const float* Wf   = (const float*)d_in[5];
    const float* bf   = (const float*)d_in[6];
    const float* Ws   = (const float*)d_in[7];
    const float* bs   = (const float*)d_in[8];
    const float* bng  = (const float*)d_in[9];
    const float* bnb  = (const float*)d_in[10];
    const float* lng  = (const float*)d_in[11];
    const float* lnb  = (const float*)d_in[12];
    const float* log_ = (const float*)d_in[13];
    const float* lob  = (const float*)d_in[14];
    const float* Wfc  = (const float*)d_in[15];
    const float* bfc  = (const float*)d_in[16];
    float* out = (float*)d_out;

    void *cursorp, *cstatp;
    cudaGetSymbolAddress(&cursorp, g_cursor);
    cudaGetSymbolAddress(&cstatp, g_cstat);

    // CSR build (once per launch)
    cudaMemsetAsync(cursorp, 0, NN * sizeof(int));
    cudaMemsetAsync(cstatp, 0, 2 * HID * sizeof(float));
    k_hist<<<(NE + 255) / 256, 256>>>(eidx);
    k_scan<<<1, 1024>>>();
    k_scatter<<<(NE + 255) / 256, 256>>>(eidx);
    k_rbf<<<(NE + 255) / 256, 256>>>(dist);
    k_embed<<<NN, HID>>>(x, Wn, bn);

    for (int l = 0; l < NL; l++) {
        k_proj<<<(NN * 32) / 256, 256>>>(Wf, Ws, l);
        k_edge<<<NN / NPB, HID>>>(Wf, bf, Ws, bs, l);
        k_bnfin<<<1, HID>>>(bng, bnb, l);
        k_update<<<NN, HID>>>(lng, lnb, l);
    }
    k_out<<<NN, HID>>>(log_, lob, Wfc, bfc, out);
}

// round 5
// speedup vs baseline: 1.2823x; 1.2569x over previous
#include <cuda_runtime.h>
#include <math.h>

#define NN   20000
#define NE   320000
#define FIN  6
#define HID  128
#define NCLS 21
#define NL   4
#define NG   16
#define EPSV 1e-5f
#define NPB  4          // nodes per block in edge kernel
#define BM   128        // GEMM tile: nodes per block
#define NBLK ((NN + BM - 1) / BM)

// ---------------- scratch (device globals; no runtime allocation) ----------
__device__ float g_e[NE * NG];         // RBF expansion, CSR edge order [E,16]
__device__ float g_h[NN * HID];        // node features
__device__ float g_pi[NN * HID * 2];   // interleaved (f,s) dst-path projection
__device__ float g_pj[NN * HID * 2];   // interleaved (f,s) src-path projection
__device__ float g_agg[NN * HID];      // aggregated messages
__device__ float g_cstat[2 * HID];     // BN column sum / sumsq
__device__ float g_bnsc[HID];
__device__ float g_bnsh[HID];
__device__ int   g_rowptr[NN + 1];     // CSR row pointers (by dst)
__device__ int   g_cursor[NN];         // degree counter / scatter cursor
__device__ int   g_csrc[NE];           // src node per CSR slot
__device__ int   g_ceid[NE];           // original edge id per CSR slot

// ---------------- CSR build ------------------------------------------------
__global__ void k_hist(const int* __restrict__ eidx) {
    int e = blockIdx.x * blockDim.x + threadIdx.x;
    if (e < NE) atomicAdd(&g_cursor[eidx[NE + e]], 1);
}

__global__ void k_scan() {   // single block, 1024 threads
    __shared__ int sp_[1024];
    int t = threadIdx.x;
    const int CH = 20;
    int base = t * CH;
    int lim = min(base + CH, NN);
    int sum = 0;
    for (int i = base; i < lim; i++) sum += g_cursor[i];
    sp_[t] = sum;
    __syncthreads();
    for (int off = 1; off < 1024; off <<= 1) {
        int v = (t >= off) ? sp_[t - off] : 0;
        __syncthreads();
        sp_[t] += v;
        __syncthreads();
    }
    int run = (t > 0) ? sp_[t - 1] : 0;
    for (int i = base; i < lim; i++) {
        int d = g_cursor[i];
        g_rowptr[i] = run;
        g_cursor[i] = run;   // reset cursor to row start for scatter
        run += d;
    }
    if (t == 0) g_rowptr[NN] = NE;
}

__global__ void k_scatter(const int* __restrict__ eidx) {
    int e = blockIdx.x * blockDim.x + threadIdx.x;
    if (e >= NE) return;
    int src = eidx[e];
    int dst = eidx[NE + e];
    int pos = atomicAdd(&g_cursor[dst], 1);
    g_csrc[pos] = src;
    g_ceid[pos] = e;
}

// ---------------- RBF expansion in CSR order -------------------------------
__global__ void k_rbf(const float* __restrict__ dist) {
    int i = blockIdx.x * blockDim.x + threadIdx.x;
    if (i >= NE) return;
    float d = dist[g_ceid[i]];
    const float coeff = -1.7578125f;            // -0.5 / (8/15)^2
    const float step  = 8.0f / 15.0f;
    float4* p = reinterpret_cast<float4*>(g_e + (size_t)i * NG);
#pragma unroll
    for (int j = 0; j < 4; j++) {
        float4 v;
        float dd;
        dd = d - (4 * j + 0) * step; v.x = __expf(coeff * dd * dd);
        dd = d - (4 * j + 1) * step; v.y = __expf(coeff * dd * dd);
        dd = d - (4 * j + 2) * step; v.z = __expf(coeff * dd * dd);
        dd = d - (4 * j + 3) * step; v.w = __expf(coeff * dd * dd);
        p[j] = v;
    }
}

// ---------------- node embedding -------------------------------------------
__global__ __launch_bounds__(HID) void k_embed(const float* __restrict__ x,
                                               const float* __restrict__ Wn,
                                               const float* __restrict__ bn) {
    int n = blockIdx.x, c = threadIdx.x;
    const float* xr = x + (size_t)n * FIN;
    float a = bn[c];
#pragma unroll
    for (int k = 0; k < FIN; k++) a = fmaf(__ldg(&xr[k]), Wn[k * HID + c], a);
    g_h[(size_t)n * HID + c] = a;
}

// ---------------- tiled GEMM projection ------------------------------------
// grid = (NBLK, 4).  blockIdx.y: bit0 = f(0)/s(1) matrix, bit1 = i(0)/j(1) path.
// C_tile[128 nodes][128 cols] = H_tile[128][128] x W[128][128]
__global__ __launch_bounds__(256) void k_proj(const float* __restrict__ Wf,
                                              const float* __restrict__ Ws,
                                              int l) {
    __shared__ float shH[BM][HID];     // [m][k]
    __shared__ float shW[HID][HID];    // [k][n]
    int tid = threadIdx.x;
    int fs   = blockIdx.y & 1;         // 0 -> Wf, 1 -> Ws
    int path = blockIdx.y >> 1;        // 0 -> i (rows 0..127), 1 -> j (rows 128..255)
    const float* Wl = (fs == 0 ? Wf : Ws) + (size_t)l * 272 * HID + (size_t)path * HID * HID;
    float* outp = (path == 0) ? g_pi : g_pj;
    int m0 = blockIdx.x * BM;

    // stage tiles: 4096 float4 each, 256 threads -> 16 each
#pragma unroll
    for (int i = 0; i < 16; i++) {
        int idx = tid + i * 256;           // float4 index
        int r = idx >> 5, q = idx & 31;
        int node = min(m0 + r, NN - 1);
        reinterpret_cast<float4*>(&shH[r][0])[q] =
            reinterpret_cast<const float4*>(g_h + (size_t)node * HID)[q];
        reinterpret_cast<float4*>(&shW[r][0])[q] =
            reinterpret_cast<const float4*>(Wl + (size_t)r * HID)[q];
    }
    __syncthreads();

    int nt = (tid & 15) * 8;   // col base
    int mt = (tid >> 4) * 8;   // local row base
    float acc[8][8];
#pragma unroll
    for (int i = 0; i < 8; i++)
#pragma unroll
        for (int j = 0; j < 8; j++) acc[i][j] = 0.f;

#pragma unroll 8
    for (int k = 0; k < HID; k++) {
        float b[8];
        float4 b0 = *reinterpret_cast<float4*>(&shW[k][nt]);
        float4 b1 = *reinterpret_cast<float4*>(&shW[k][nt + 4]);
        b[0] = b0.x; b[1] = b0.y; b[2] = b0.z; b[3] = b0.w;
        b[4] = b1.x; b[5] = b1.y; b[6] = b1.z; b[7] = b1.w;
        float a[8];
#pragma unroll
        for (int i = 0; i < 8; i++) a[i] = shH[mt + i][k];
#pragma unroll
        for (int i = 0; i < 8; i++)
#pragma unroll
            for (int j = 0; j < 8; j++)
                acc[i][j] = fmaf(a[i], b[j], acc[i][j]);
    }

    // write interleaved (f,s): out[node][2*col + fs]
#pragma unroll
    for (int i = 0; i < 8; i++) {
        int node = m0 + mt + i;
        if (node >= NN) break;
        float* orow = outp + (size_t)node * (2 * HID) + fs;
#pragma unroll
        for (int j = 0; j < 8; j++) orow[2 * (nt + j)] = acc[i][j];
    }
}

// ---------------- CSR edge aggregation (no atomics) + fused BN stats -------
__global__ __launch_bounds__(HID) void k_edge(const float* __restrict__ Wf,
                                              const float* __restrict__ bf,
                                              const float* __restrict__ Ws,
                                              const float* __restrict__ bs,
                                              int l) {
    __shared__ float4 se[512];     // up to 128 edges * 16 floats of RBF
    __shared__ int ssrc[128];
    int c = threadIdx.x;
    const float* Wfe = Wf + (size_t)l * 272 * HID + 256 * HID;
    const float* Wse = Ws + (size_t)l * 272 * HID + 256 * HID;
    float wfe[NG], wse[NG];
#pragma unroll
    for (int k = 0; k < NG; k++) {
        wfe[k] = __ldg(&Wfe[k * HID + c]);
        wse[k] = __ldg(&Wse[k * HID + c]);
    }
    float bfc = __ldg(&bf[l * HID + c]);
    float bsc = __ldg(&bs[l * HID + c]);
    for (int nn = 0; nn < NPB; nn++) {
        int n = blockIdx.x * NPB + nn;
        float2 pi = *reinterpret_cast<const float2*>(g_pi + (size_t)n * (2 * HID) + 2 * c);
        float zfb = pi.x + bfc;
        float zsb = pi.y + bsc;
        int start = g_rowptr[n], end = g_rowptr[n + 1];
        float acc = 0.f;
        for (int j0 = start; j0 < end; j0 += 128) {
            int cnt = min(128, end - j0);
            if (c < cnt) ssrc[c] = g_csrc[j0 + c];
            const float4* ge4 = reinterpret_cast<const float4*>(g_e) + (size_t)j0 * 4;
            for (int t = c; t < cnt * 4; t += HID) se[t] = ge4[t];
            __syncthreads();
#pragma unroll 2
            for (int i = 0; i < cnt; i++) {
                int s = ssrc[i];
                float2 pj = *reinterpret_cast<const float2*>(g_pj + (size_t)s * (2 * HID) + 2 * c);
                float4 ea = se[i * 4 + 0], eb = se[i * 4 + 1];
                float4 ec = se[i * 4 + 2], ed = se[i * 4 + 3];
                float zf = zfb + pj.x;
                float zs = zsb + pj.y;
                float f0 = fmaf(ea.x, wfe[0],  fmaf(ea.y, wfe[1],  fmaf(ea.z, wfe[2],  ea.w * wfe[3])));
                float f1 = fmaf(eb.x, wfe[4],  fmaf(eb.y, wfe[5],  fmaf(eb.z, wfe[6],  eb.w * wfe[7])));
                float f2 = fmaf(ec.x, wfe[8],  fmaf(ec.y, wfe[9],  fmaf(ec.z, wfe[10], ec.w * wfe[11])));
                float f3 = fmaf(ed.x, wfe[12], fmaf(ed.y, wfe[13], fmaf(ed.z, wfe[14], ed.w * wfe[15])));
                float s0 = fmaf(ea.x, wse[0],  fmaf(ea.y, wse[1],  fmaf(ea.z, wse[2],  ea.w * wse[3])));
                float s1 = fmaf(eb.x, wse[4],  fmaf(eb.y, wse[5],  fmaf(eb.z, wse[6],  eb.w * wse[7])));
                float s2 = fmaf(ec.x, wse[8],  fmaf(ec.y, wse[9],  fmaf(ec.z, wse[10], ec.w * wse[11])));
                float s3 = fmaf(ed.x, wse[12], fmaf(ed.y, wse[13], fmaf(ed.z, wse[14], ed.w * wse[15])));
                zf += (f0 + f1) + (f2 + f3);
                zs += (s0 + s1) + (s2 + s3);
                float fg = __fdividef(1.0f, 1.0f + __expf(-zf));
                float sp = fmaxf(zs, 0.0f) + __logf(1.0f + __expf(-fabsf(zs)));
                acc = fmaf(fg, sp, acc);
            }
            __syncthreads();
        }
        g_agg[(size_t)n * HID + c] = acc;
        atomicAdd(&g_cstat[c], acc);              // REDG, fire-and-forget
        atomicAdd(&g_cstat[HID + c], acc * acc);
    }
}

// ---------------- BN finalize (also zeros cstat for next layer) ------------
__global__ void k_bnfin(const float* __restrict__ bn_g,
                        const float* __restrict__ bn_b, int l) {
    int c = threadIdx.x;
    float sum = g_cstat[c], sq = g_cstat[HID + c];
    g_cstat[c] = 0.f;
    g_cstat[HID + c] = 0.f;
    float mu = sum * (1.0f / NN);
    float var = sq * (1.0f / NN) - mu * mu;
    float sc = bn_g[l * HID + c] * rsqrtf(var + EPSV);
    g_bnsc[c] = sc;
    g_bnsh[c] = fmaf(-mu, sc, bn_b[l * HID + c]);
}

// ---------------- fused BN-apply + residual + LayerNorm + ReLU + residual --
__global__ __launch_bounds__(HID) void k_update(const float* __restrict__ ln_g,
                                                const float* __restrict__ ln_b,
                                                int l) {
    int n = blockIdx.x, c = threadIdx.x;
    float h = g_h[(size_t)n * HID + c];
    float v = fmaf(g_agg[(size_t)n * HID + c], g_bnsc[c], g_bnsh[c]) + h;
    float s = v, q = v * v;
#pragma unroll
    for (int o = 16; o > 0; o >>= 1) {
        s += __shfl_xor_sync(0xffffffffu, s, o);
        q += __shfl_xor_sync(0xffffffffu, q, o);
    }
    __shared__ float ss[4], sq[4], smv[2];
    int w = c >> 5;
    if ((c & 31) == 0) { ss[w] = s; sq[w] = q; }
    __syncthreads();
    if (c == 0) {
        float ts = ss[0] + ss[1] + ss[2] + ss[3];
        float tq = sq[0] + sq[1] + sq[2] + sq[3];
        float m = ts * (1.0f / HID);
        float var = tq * (1.0f / HID) - m * m;
        smv[0] = m; smv[1] = rsqrtf(var + EPSV);
    }
    __syncthreads();
    float hn = fmaf((v - smv[0]) * smv[1], ln_g[l * HID + c], ln_b[l * HID + c]);
    g_h[(size_t)n * HID + c] = fmaxf(hn, 0.0f) + h;
}

// ---------------- final LayerNorm + FC -------------------------------------
__global__ __launch_bounds__(HID) void k_out(const float* __restrict__ lng,
                                             const float* __restrict__ lnb,
                                             const float* __restrict__ Wfc,
                                             const float* __restrict__ bfc,
                                             float* __restrict__ out) {
    int n = blockIdx.x, c = threadIdx.x;
    float h = g_h[(size_t)n * HID + c];
    float s = h, q = h * h;
#pragma unroll
    for (int o = 16; o > 0; o >>= 1) {
        s += __shfl_xor_sync(0xffffffffu, s, o);
        q += __shfl_xor_sync(0xffffffffu, q, o);
    }
    __shared__ float ss[4], sq[4], smv[2];
    __shared__ float sh[HID];
    int w = c >> 5;
    if ((c & 31) == 0) { ss[w] = s; sq[w] = q; }
    __syncthreads();
    if (c == 0) {
        float ts = ss[0] + ss[1] + ss[2] + ss[3];
        float tq = sq[0] + sq[1] + sq[2] + sq[3];
        float m = ts * (1.0f / HID);
        float var = tq * (1.0f / HID) - m * m;
        smv[0] = m; smv[1] = rsqrtf(var + EPSV);
    }
    __syncthreads();
    sh[c] = fmaf((h - smv[0]) * smv[1], lng[c], lnb[c]);
    __syncthreads();
    if (c < NCLS) {
        float a = bfc[c];
#pragma unroll 16
        for (int k = 0; k < HID; k++) a = fmaf(sh[k], Wfc[k * NCLS + c], a);
        out[(size_t)n * NCLS + c] = a;
    }
}

// ---------------- launch ----------------------------------------------------
extern "C" void kernel_launch(void* const* d_in, const int* in_sizes, int n_in,
                              void* d_out, int out_size) {
    const float* x    = (const float*)d_in[0];
    const int*   eidx = (const int*)  d_in[1];
    const float* dist = (const float*)d_in[2];
    const float* Wn   = (const float*)d_in[3];
    const float* bn   = (const float*)d_in[4];
    const float* Wf   = (const float*)d_in[5];
    const float* bf   = (const float*)d_in[6];
    const float* Ws   = (const float*)d_in[7];
    const float* bs   = (const float*)d_in[8];
    const float* bng  = (const float*)d_in[9];
    const float* bnb  = (const float*)d_in[10];
    const float* lng  = (const float*)d_in[11];
    const float* lnb  = (const float*)d_in[12];
    const float* log_ = (const float*)d_in[13];
    const float* lob  = (const float*)d_in[14];
    const float* Wfc  = (const float*)d_in[15];
    const float* bfc  = (const float*)d_in[16];
    float* out = (float*)d_out;

    void *cursorp, *cstatp;
    cudaGetSymbolAddress(&cursorp, g_cursor);
    cudaGetSymbolAddress(&cstatp, g_cstat);

    // CSR build (once per launch)
    cudaMemsetAsync(cursorp, 0, NN * sizeof(int));
    cudaMemsetAsync(cstatp, 0, 2 * HID * sizeof(float));
    k_hist<<<(NE + 255) / 256, 256>>>(eidx);
    k_scan<<<1, 1024>>>();
    k_scatter<<<(NE + 255) / 256, 256>>>(eidx);
    k_rbf<<<(NE + 255) / 256, 256>>>(dist);
    k_embed<<<NN, HID>>>(x, Wn, bn);

    for (int l = 0; l < NL; l++) {
        k_proj<<<dim3(NBLK, 4), 256>>>(Wf, Ws, l);
        k_edge<<<NN / NPB, HID>>>(Wf, bf, Ws, bs, l);
        k_bnfin<<<1, HID>>>(bng, bnb, l);
        k_update<<<NN, HID>>>(lng, lnb, l);
    }
    k_out<<<NN, HID>>>(log_, lob, Wfc, bfc, out);
}